// round 8
// baseline (speedup 1.0000x reference)
#include <cuda_runtime.h>
#include <cuda_bf16.h>
#include <cstdint>

namespace {
constexpr int B  = 2;
constexpr int N  = 2048;
constexpr int C  = 512;
constexpr int H  = 8;
constexpr int DH = 64;
constexpr int M  = B * N;          // 4096 tokens
constexpr int QKV_W = 3 * C * 2;   // 3072 weight rows
constexpr int PRJ_W = C * 2;       // 1024 weight rows
constexpr int PRJ_O = C;           // 512 fused outputs

constexpr int BM = 128;
constexpr int BN = 128;
constexpr int BK = 64;             // K chunk (bf16) = 128 bytes/row
constexpr int NC = 8;              // 512 / 64 chunks
// smem: A[2]x32KB (Ah+Al), Wh[2]x16KB, Wl[1]x16KB = 112 KB
constexpr int GEMM_SMEM  = 114688 + 128;

constexpr int ATTN_SMEM = 2 * 16384 + 2 * 32768;  // Qh/Ql + 2 KV stages = 96 KB
}

// Scratch (device globals — no allocation allowed)
__device__ __nv_bfloat16 g_xh[(size_t)M * C];
__device__ __nv_bfloat16 g_xl[(size_t)M * C];
__device__ __nv_bfloat16 g_Wqh[(size_t)QKV_W * C];
__device__ __nv_bfloat16 g_Wql[(size_t)QKV_W * C];
__device__ __nv_bfloat16 g_Wph[(size_t)PRJ_W * C];
__device__ __nv_bfloat16 g_Wpl[(size_t)PRJ_W * C];
__device__ __nv_bfloat16 g_aoh[(size_t)M * C];
__device__ __nv_bfloat16 g_aol[(size_t)M * C];
// attention-ready qkv, head-major: [bh][n][64], hi/lo bf16
__device__ __nv_bfloat16 g_qh[(size_t)B * H * N * DH];
__device__ __nv_bfloat16 g_ql[(size_t)B * H * N * DH];
__device__ __nv_bfloat16 g_kh[(size_t)B * H * N * DH];
__device__ __nv_bfloat16 g_kl[(size_t)B * H * N * DH];
__device__ __nv_bfloat16 g_vh[(size_t)B * H * N * DH];
__device__ __nv_bfloat16 g_vl[(size_t)B * H * N * DH];
__device__ float g_xnorm2[M];             // sum of squares of x rows
__device__ float g_aopart[(size_t)H * M]; // per-head partial sumsq of ao rows

// ---------------------------------------------------------------------------
// PTX helpers (compute_103-safe: cp.async, ldmatrix, mma.sync bf16)
// ---------------------------------------------------------------------------
__device__ __forceinline__ uint32_t smem_u32(const void* p) {
    return (uint32_t)__cvta_generic_to_shared(p);
}
__device__ __forceinline__ void cp16(uint32_t s, const void* g) {
    asm volatile("cp.async.cg.shared.global [%0], [%1], 16;\n" :: "r"(s), "l"(g));
}
__device__ __forceinline__ uint32_t sw128(uint32_t off) {
    return off ^ ((off >> 3) & 0x70);
}
__device__ __forceinline__ void ldm_x4(uint32_t* r, uint32_t addr) {
    asm volatile("ldmatrix.sync.aligned.m8n8.x4.shared.b16 {%0,%1,%2,%3}, [%4];"
                 : "=r"(r[0]), "=r"(r[1]), "=r"(r[2]), "=r"(r[3]) : "r"(addr));
}
__device__ __forceinline__ void ldm_x4_t(uint32_t* r, uint32_t addr) {
    asm volatile("ldmatrix.sync.aligned.m8n8.x4.trans.shared.b16 {%0,%1,%2,%3}, [%4];"
                 : "=r"(r[0]), "=r"(r[1]), "=r"(r[2]), "=r"(r[3]) : "r"(addr));
}
__device__ __forceinline__ void mma16816(float* c, const uint32_t* a,
                                         const uint32_t* b) {
    asm volatile(
        "mma.sync.aligned.m16n8k16.row.col.f32.bf16.bf16.f32 "
        "{%0,%1,%2,%3}, {%4,%5,%6,%7}, {%8,%9}, {%0,%1,%2,%3};"
        : "+f"(c[0]), "+f"(c[1]), "+f"(c[2]), "+f"(c[3])
        : "r"(a[0]), "r"(a[1]), "r"(a[2]), "r"(a[3]), "r"(b[0]), "r"(b[1]));
}
__device__ __forceinline__ uint32_t packbf(float lo, float hi) {
    __nv_bfloat162 t = __floats2bfloat162_rn(lo, hi);
    return *(uint32_t*)&t;
}
__device__ __forceinline__ void split_pack(float lo, float hi,
                                           uint32_t& h, uint32_t& l) {
    h = packbf(lo, hi);
    __nv_bfloat162 hv = *(__nv_bfloat162*)&h;
    l = packbf(lo - __bfloat162float(hv.x), hi - __bfloat162float(hv.y));
}

// ---------------------------------------------------------------------------
// prep: per-row sum-of-squares + bf16 hi/lo split (x)
// ---------------------------------------------------------------------------
__global__ void prep_act_kernel(const float* __restrict__ A,
                                __nv_bfloat16* __restrict__ Ah,
                                __nv_bfloat16* __restrict__ Al,
                                float* __restrict__ norm2) {
    int r = blockIdx.x, t = threadIdx.x;
    float4 v = ((const float4*)(A + (size_t)r * C))[t];
    float s = v.x * v.x + v.y * v.y + v.z * v.z + v.w * v.w;
    #pragma unroll
    for (int o = 16; o; o >>= 1) s += __shfl_xor_sync(0xffffffffu, s, o);
    __shared__ float sm[4];
    if ((t & 31) == 0) sm[t >> 5] = s;
    __syncthreads();
    if (t == 0) norm2[r] = sm[0] + sm[1] + sm[2] + sm[3];
    float va[4] = {v.x, v.y, v.z, v.w};
    #pragma unroll
    for (int j = 0; j < 4; j++) {
        __nv_bfloat16 h = __float2bfloat16(va[j]);
        __nv_bfloat16 l = __float2bfloat16(va[j] - __bfloat162float(h));
        Ah[(size_t)r * C + t * 4 + j] = h;
        Al[(size_t)r * C + t * 4 + j] = l;
    }
}

// prep: normalize weight rows, maxout partners ADJACENT (o->2o, o+half->2o+1)
__global__ void prep_w_kernel(const float* __restrict__ W,
                              __nv_bfloat16* __restrict__ Dh,
                              __nv_bfloat16* __restrict__ Dl, int half) {
    int r = blockIdx.x, t = threadIdx.x;
    float4 v = ((const float4*)(W + (size_t)r * C))[t];
    float s = v.x * v.x + v.y * v.y + v.z * v.z + v.w * v.w;
    #pragma unroll
    for (int o = 16; o; o >>= 1) s += __shfl_xor_sync(0xffffffffu, s, o);
    __shared__ float sm[4];
    if ((t & 31) == 0) sm[t >> 5] = s;
    __syncthreads();
    float inv = rsqrtf(sm[0] + sm[1] + sm[2] + sm[3]);
    int dr = (r < half) ? 2 * r : 2 * (r - half) + 1;
    float va[4] = {v.x, v.y, v.z, v.w};
    #pragma unroll
    for (int j = 0; j < 4; j++) {
        float w = va[j] * inv;
        __nv_bfloat16 h = __float2bfloat16(w);
        __nv_bfloat16 l = __float2bfloat16(w - __bfloat162float(h));
        Dh[(size_t)dr * C + t * 4 + j] = h;
        Dl[(size_t)dr * C + t * 4 + j] = l;
    }
}

// ---------------------------------------------------------------------------
// mma.sync bcos GEMM (bf16x3), chunk-joint: per 64-K chunk load {Ah,Al,Wh,Wl}
// once, run the 3 split phases against resident tiles.
// MODE 0: proj — norms from 8 per-head partials, fp32 out.
// MODE 1: qkv — norms = x sumsq, bf16 split scatter head-major (q * 0.125).
// ---------------------------------------------------------------------------
template <int MODE>
__global__ __launch_bounds__(256, 2) void tc_gemm_kernel(
    const __nv_bfloat16* __restrict__ Ah, const __nv_bfloat16* __restrict__ Al,
    const __nv_bfloat16* __restrict__ Wh, const __nv_bfloat16* __restrict__ Wl,
    const float* __restrict__ norms, float* __restrict__ out, int nout,
    __nv_bfloat16* __restrict__ qh, __nv_bfloat16* __restrict__ ql,
    __nv_bfloat16* __restrict__ kh, __nv_bfloat16* __restrict__ kl,
    __nv_bfloat16* __restrict__ vh, __nv_bfloat16* __restrict__ vl)
{
    extern __shared__ char smem[];
    const uint32_t sbase  = (smem_u32(smem) + 127) & ~127u;
    const uint32_t aBuf0  = sbase;           // 2 x 32KB (Ah 16K | Al 16K)
    const uint32_t whBuf0 = sbase + 65536;   // 2 x 16KB
    const uint32_t wlBuf  = sbase + 98304;   // 1 x 16KB
    const int tid = threadIdx.x;
    const int lane = tid & 31;
    const int warp = tid >> 5;
    const int wm = warp >> 2;
    const int wn = warp & 3;
    const int bm = blockIdx.y * BM;
    const int bc = blockIdx.x * BN;

    auto loadA = [&](int k) {                 // Ah + Al chunk, 1 group
        uint32_t ab = aBuf0 + (k & 1) * 32768;
        int k0 = k * BK;
        #pragma unroll
        for (int u = 0; u < 4; u++) {
            int c = tid + u * 256;
            int row = c >> 3, seg = c & 7;
            uint32_t sw = sw128(row * 128 + seg * 16);
            cp16(ab + sw,         Ah + (size_t)(bm + row) * C + k0 + seg * 8);
            cp16(ab + 16384 + sw, Al + (size_t)(bm + row) * C + k0 + seg * 8);
        }
        asm volatile("cp.async.commit_group;\n");
    };
    auto loadW = [&](const __nv_bfloat16* W, uint32_t buf, int k) {  // 1 group
        int k0 = k * BK;
        #pragma unroll
        for (int u = 0; u < 4; u++) {
            int c = tid + u * 256;
            int row = c >> 3, seg = c & 7;
            cp16(buf + sw128(row * 128 + seg * 16),
                 W + (size_t)(bc + row) * C + k0 + seg * 8);
        }
        asm volatile("cp.async.commit_group;\n");
    };

    float acc[4][4][4];
    #pragma unroll
    for (int i = 0; i < 4; i++)
        #pragma unroll
        for (int j = 0; j < 4; j++)
            #pragma unroll
            for (int q = 0; q < 4; q++) acc[i][j][q] = 0.f;

    auto phase = [&](uint32_t ab, uint32_t bb) {   // 64-K MMA pass
        #pragma unroll
        for (int ks = 0; ks < 4; ks++) {
            uint32_t afrag[4][4], bfrag[2][4];
            #pragma unroll
            for (int mt = 0; mt < 4; mt++) {
                int row = wm * 64 + mt * 16 + (lane & 15);
                int seg = ks * 2 + (lane >> 4);
                ldm_x4(afrag[mt], ab + sw128(row * 128 + seg * 16));
            }
            #pragma unroll
            for (int p = 0; p < 2; p++) {
                int row = wn * 32 + p * 16 + (lane & 7) + ((lane >> 4) << 3);
                int seg = ks * 2 + ((lane >> 3) & 1);
                ldm_x4(bfrag[p], bb + sw128(row * 128 + seg * 16));
            }
            #pragma unroll
            for (int mt = 0; mt < 4; mt++)
                #pragma unroll
                for (int nt = 0; nt < 4; nt++)
                    mma16816(acc[mt][nt], afrag[mt], &bfrag[nt >> 1][(nt & 1) * 2]);
        }
    };

    loadA(0); loadW(Wh, whBuf0, 0); loadW(Wl, wlBuf, 0);

    for (int k = 0; k < NC; k++) {
        if (k + 1 < NC) {
            loadA(k + 1);
            loadW(Wh, whBuf0 + ((k + 1) & 1) * 16384, k + 1);
            asm volatile("cp.async.wait_group 2;\n" ::: "memory");
        } else {
            asm volatile("cp.async.wait_group 0;\n" ::: "memory");
        }
        __syncthreads();
        uint32_t ab = aBuf0 + (k & 1) * 32768;
        uint32_t wh = whBuf0 + (k & 1) * 16384;
        phase(ab, wh);            // Ah . Wh
        phase(ab, wlBuf);         // Ah . Wl
        __syncthreads();          // all warps done reading Wl_k
        if (k + 1 < NC) loadW(Wl, wlBuf, k + 1);
        phase(ab + 16384, wh);    // Al . Wh
    }

    const float sc = rsqrtf((float)C);
    const int g = lane >> 2, tig = lane & 3;

    __nv_bfloat16 *dsth = nullptr, *dstl = nullptr;
    float qscale = 1.f;
    int hh = 0;
    if (MODE == 1) {
        int colbase = bc >> 1;
        int sect = colbase >> 9;
        hh = (colbase & 511) >> 6;
        if (sect == 0)      { dsth = qh; dstl = ql; qscale = 0.125f; }
        else if (sect == 1) { dsth = kh; dstl = kl; }
        else                { dsth = vh; dstl = vl; }
    }

    #pragma unroll
    for (int mt = 0; mt < 4; mt++) {
        int m0 = bm + wm * 64 + mt * 16;
        int r0 = m0 + g, r1 = m0 + g + 8;
        float inv0, inv1;
        if (MODE == 0) {
            float s0 = 0.f, s1 = 0.f;
            #pragma unroll
            for (int p = 0; p < H; p++) {
                s0 += norms[(size_t)p * M + r0];
                s1 += norms[(size_t)p * M + r1];
            }
            inv0 = sc * rsqrtf(s0);
            inv1 = sc * rsqrtf(s1);
        } else {
            inv0 = sc * rsqrtf(norms[r0]);
            inv1 = sc * rsqrtf(norms[r1]);
        }
        #pragma unroll
        for (int nt = 0; nt < 4; nt++) {
            float v0 = fmaxf(acc[mt][nt][0], acc[mt][nt][1]);
            v0 = v0 * fabsf(v0) * inv0;
            float v1 = fmaxf(acc[mt][nt][2], acc[mt][nt][3]);
            v1 = v1 * fabsf(v1) * inv1;
            if (MODE == 0) {
                int col = (bc >> 1) + wn * 16 + nt * 4 + tig;
                out[(size_t)r0 * nout + col] = v0;
                out[(size_t)r1 * nout + col] = v1;
            } else {
                int d = wn * 16 + nt * 4 + tig;
                v0 *= qscale; v1 *= qscale;
                __nv_bfloat16 h0 = __float2bfloat16(v0);
                __nv_bfloat16 h1 = __float2bfloat16(v1);
                size_t i0 = ((size_t)(((r0 >> 11) << 3) + hh) * N + (r0 & 2047)) * DH + d;
                size_t i1 = ((size_t)(((r1 >> 11) << 3) + hh) * N + (r1 & 2047)) * DH + d;
                dsth[i0] = h0; dstl[i0] = __float2bfloat16(v0 - __bfloat162float(h0));
                dsth[i1] = h1; dstl[i1] = __float2bfloat16(v1 - __bfloat162float(h1));
            }
        }
    }
}

// ---------------------------------------------------------------------------
// Flash attention, mma.sync bf16 split. Block = 128 q-rows of one (b,h).
// Epilogue writes bf16 hi/lo ao directly + per-(head,row) partial sumsq.
// ---------------------------------------------------------------------------
__global__ __launch_bounds__(256, 2) void attn_mma_kernel(
    const __nv_bfloat16* __restrict__ qh, const __nv_bfloat16* __restrict__ ql,
    const __nv_bfloat16* __restrict__ kh, const __nv_bfloat16* __restrict__ kl,
    const __nv_bfloat16* __restrict__ vh, const __nv_bfloat16* __restrict__ vl,
    __nv_bfloat16* __restrict__ aoh, __nv_bfloat16* __restrict__ aol,
    float* __restrict__ aopart)
{
    extern __shared__ char smem[];
    const uint32_t sQh = smem_u32(smem);
    const uint32_t sQl = sQh + 16384;
    const uint32_t sKV = sQl + 16384;       // 2 stages x {Kh,Kl,Vh,Vl} x 8KB

    const int bh = blockIdx.y;
    const int q0 = blockIdx.x * 128;
    const int tid = threadIdx.x;
    const int lane = tid & 31;
    const int warp = tid >> 5;
    const int g = lane >> 2, tig = lane & 3;
    const int wr = warp * 16;
    const size_t tok0 = (size_t)bh * N;

    {
        const __nv_bfloat16* srcs[2] = {qh, ql};
        #pragma unroll
        for (int u = 0; u < 8; u++) {
            const __nv_bfloat16* src = srcs[u >> 2];
            uint32_t dst = (u >> 2) ? sQl : sQh;
            int c = (u & 3) * 256 + tid;
            int row = c >> 3, seg = c & 7;
            cp16(dst + sw128(row * 128 + seg * 16),
                 src + (tok0 + q0 + row) * DH + seg * 8);
        }
    }
    auto load_kv = [&](int t) {
        int kv0 = t * 64;
        uint32_t sbase = sKV + (t & 1) * 32768;
        const __nv_bfloat16* srcs[4] = {kh, kl, vh, vl};
        #pragma unroll
        for (int u = 0; u < 8; u++) {
            const __nv_bfloat16* src = srcs[u >> 1];
            uint32_t dst = sbase + (u >> 1) * 8192;
            int c = (u & 1) * 256 + tid;
            int row = c >> 3, seg = c & 7;
            cp16(dst + sw128(row * 128 + seg * 16),
                 src + (tok0 + kv0 + row) * DH + seg * 8);
        }
        asm volatile("cp.async.commit_group;\n");
    };
    load_kv(0);   // group 0 = Q + KV0

    float o[8][4];
    #pragma unroll
    for (int nt = 0; nt < 8; nt++)
        #pragma unroll
        for (int q = 0; q < 4; q++) o[nt][q] = 0.f;
    float m0r = -1e30f, m1r = -1e30f, l0r = 0.f, l1r = 0.f;

    const int NKV = N / 64;
    for (int t = 0; t < NKV; t++) {
        if (t + 1 < NKV) {
            load_kv(t + 1);
            asm volatile("cp.async.wait_group 1;\n" ::: "memory");
        } else {
            asm volatile("cp.async.wait_group 0;\n" ::: "memory");
        }
        __syncthreads();
        uint32_t sK = sKV + (t & 1) * 32768;       // Kh
        uint32_t sKl = sK + 8192;
        uint32_t sV = sK + 16384;                  // Vh
        uint32_t sVl = sK + 24576;

        // ---- S = Q K^T (3 split terms)
        float s[8][4];
        #pragma unroll
        for (int nt = 0; nt < 8; nt++)
            #pragma unroll
            for (int q = 0; q < 4; q++) s[nt][q] = 0.f;

        #pragma unroll
        for (int kt = 0; kt < 4; kt++) {
            uint32_t aH[4], aL[4];
            {
                int row = wr + (lane & 15);
                int seg = kt * 2 + (lane >> 4);
                uint32_t off = sw128(row * 128 + seg * 16);
                ldm_x4(aH, sQh + off);
                ldm_x4(aL, sQl + off);
            }
            #pragma unroll
            for (int bn = 0; bn < 4; bn++) {
                int row = bn * 16 + (lane & 7) + ((lane >> 4) << 3);
                int seg = kt * 2 + ((lane >> 3) & 1);
                uint32_t off = sw128(row * 128 + seg * 16);
                uint32_t bH[4], bL[4];
                ldm_x4(bH, sK + off);
                ldm_x4(bL, sKl + off);
                #pragma unroll
                for (int sub = 0; sub < 2; sub++) {
                    int nt = bn * 2 + sub;
                    mma16816(s[nt], aH, &bH[sub * 2]);
                    mma16816(s[nt], aL, &bH[sub * 2]);
                    mma16816(s[nt], aH, &bL[sub * 2]);
                }
            }
        }

        // ---- online softmax (rows g and g+8, warp-local over tig lanes)
        float tm0 = -1e30f, tm1 = -1e30f;
        #pragma unroll
        for (int nt = 0; nt < 8; nt++) {
            tm0 = fmaxf(tm0, fmaxf(s[nt][0], s[nt][1]));
            tm1 = fmaxf(tm1, fmaxf(s[nt][2], s[nt][3]));
        }
        tm0 = fmaxf(tm0, __shfl_xor_sync(0xffffffffu, tm0, 1));
        tm0 = fmaxf(tm0, __shfl_xor_sync(0xffffffffu, tm0, 2));
        tm1 = fmaxf(tm1, __shfl_xor_sync(0xffffffffu, tm1, 1));
        tm1 = fmaxf(tm1, __shfl_xor_sync(0xffffffffu, tm1, 2));
        float mn0 = fmaxf(m0r, tm0), mn1 = fmaxf(m1r, tm1);
        float rs0 = __expf(m0r - mn0), rs1 = __expf(m1r - mn1);
        float ts0 = 0.f, ts1 = 0.f;
        #pragma unroll
        for (int nt = 0; nt < 8; nt++) {
            s[nt][0] = __expf(s[nt][0] - mn0); ts0 += s[nt][0];
            s[nt][1] = __expf(s[nt][1] - mn0); ts0 += s[nt][1];
            s[nt][2] = __expf(s[nt][2] - mn1); ts1 += s[nt][2];
            s[nt][3] = __expf(s[nt][3] - mn1); ts1 += s[nt][3];
        }
        ts0 += __shfl_xor_sync(0xffffffffu, ts0, 1);
        ts0 += __shfl_xor_sync(0xffffffffu, ts0, 2);
        ts1 += __shfl_xor_sync(0xffffffffu, ts1, 1);
        ts1 += __shfl_xor_sync(0xffffffffu, ts1, 2);
        l0r = l0r * rs0 + ts0; m0r = mn0;
        l1r = l1r * rs1 + ts1; m1r = mn1;
        #pragma unroll
        for (int nt = 0; nt < 8; nt++) {
            o[nt][0] *= rs0; o[nt][1] *= rs0;
            o[nt][2] *= rs1; o[nt][3] *= rs1;
        }

        // ---- P fragments (A-operand layout), hi/lo split in registers
        uint32_t ph[4][4], pl[4][4];
        #pragma unroll
        for (int kt = 0; kt < 4; kt++) {
            split_pack(s[2 * kt][0],     s[2 * kt][1],     ph[kt][0], pl[kt][0]);
            split_pack(s[2 * kt][2],     s[2 * kt][3],     ph[kt][1], pl[kt][1]);
            split_pack(s[2 * kt + 1][0], s[2 * kt + 1][1], ph[kt][2], pl[kt][2]);
            split_pack(s[2 * kt + 1][2], s[2 * kt + 1][3], ph[kt][3], pl[kt][3]);
        }

        // ---- O += P V  (PhVh + PlVh + PhVl), V frags via ldmatrix.trans
        #pragma unroll
        for (int kt = 0; kt < 4; kt++) {
            #pragma unroll
            for (int bn = 0; bn < 4; bn++) {
                int mat = lane >> 3, i = lane & 7;
                int row = kt * 16 + (mat & 1) * 8 + i;
                int coloff = (bn * 16 + (mat >> 1) * 8) * 2;
                uint32_t off = sw128(row * 128 + coloff);
                uint32_t bH[4], bL[4];
                ldm_x4_t(bH, sV + off);
                ldm_x4_t(bL, sVl + off);
                #pragma unroll
                for (int sub = 0; sub < 2; sub++) {
                    int nt = bn * 2 + sub;
                    mma16816(o[nt], ph[kt], &bH[sub * 2]);
                    mma16816(o[nt], pl[kt], &bH[sub * 2]);
                    mma16816(o[nt], ph[kt], &bL[sub * 2]);
                }
            }
        }
        __syncthreads();
    }

    // ---- epilogue: /l, bf16 hi/lo split, partial sumsq per (head,row)
    const int b = bh >> 3;
    const int h = bh & 7;
    const int hoff = h * DH;
    const float inv0 = 1.f / l0r, inv1 = 1.f / l1r;
    const int row0 = q0 + wr + g;
    const size_t base0 = (size_t)(b * N + row0) * C + hoff + 2 * tig;
    const size_t base1 = (size_t)(b * N + row0 + 8) * C + hoff + 2 * tig;
    float ss0 = 0.f, ss1 = 0.f;
    #pragma unroll
    for (int nt = 0; nt < 8; nt++) {
        float a0 = o[nt][0] * inv0, a1 = o[nt][1] * inv0;
        float b0 = o[nt][2] * inv1, b1 = o[nt][3] * inv1;
        ss0 += a0 * a0 + a1 * a1;
        ss1 += b0 * b0 + b1 * b1;
        uint32_t h0, l0, h1, l1;
        split_pack(a0, a1, h0, l0);
        split_pack(b0, b1, h1, l1);
        *(uint32_t*)(aoh + base0 + nt * 8) = h0;
        *(uint32_t*)(aol + base0 + nt * 8) = l0;
        *(uint32_t*)(aoh + base1 + nt * 8) = h1;
        *(uint32_t*)(aol + base1 + nt * 8) = l1;
    }
    ss0 += __shfl_xor_sync(0xffffffffu, ss0, 1);
    ss0 += __shfl_xor_sync(0xffffffffu, ss0, 2);
    ss1 += __shfl_xor_sync(0xffffffffu, ss1, 1);
    ss1 += __shfl_xor_sync(0xffffffffu, ss1, 2);
    if (tig == 0) {
        aopart[(size_t)h * M + b * N + row0]     = ss0;
        aopart[(size_t)h * M + b * N + row0 + 8] = ss1;
    }
}

// ---------------------------------------------------------------------------

extern "C" void kernel_launch(void* const* d_in, const int* in_sizes, int n_in,
                              void* d_out, int out_size) {
    (void)in_sizes; (void)n_in; (void)out_size;
    const float* x    = (const float*)d_in[0];
    const float* Wqkv = (const float*)d_in[1];
    const float* Wprj = (const float*)d_in[2];
    float* out = (float*)d_out;

    __nv_bfloat16 *pxh, *pxl, *pWqh, *pWql, *pWph, *pWpl, *paoh, *paol;
    __nv_bfloat16 *pqh, *pql, *pkh, *pkl, *pvh, *pvl;
    float *pxn2, *papart;
    cudaGetSymbolAddress((void**)&pxh,  g_xh);
    cudaGetSymbolAddress((void**)&pxl,  g_xl);
    cudaGetSymbolAddress((void**)&pWqh, g_Wqh);
    cudaGetSymbolAddress((void**)&pWql, g_Wql);
    cudaGetSymbolAddress((void**)&pWph, g_Wph);
    cudaGetSymbolAddress((void**)&pWpl, g_Wpl);
    cudaGetSymbolAddress((void**)&paoh, g_aoh);
    cudaGetSymbolAddress((void**)&paol, g_aol);
    cudaGetSymbolAddress((void**)&pqh,  g_qh);
    cudaGetSymbolAddress((void**)&pql,  g_ql);
    cudaGetSymbolAddress((void**)&pkh,  g_kh);
    cudaGetSymbolAddress((void**)&pkl,  g_kl);
    cudaGetSymbolAddress((void**)&pvh,  g_vh);
    cudaGetSymbolAddress((void**)&pvl,  g_vl);
    cudaGetSymbolAddress((void**)&pxn2, g_xnorm2);
    cudaGetSymbolAddress((void**)&papart, g_aopart);

    cudaFuncSetAttribute(tc_gemm_kernel<0>,
                         cudaFuncAttributeMaxDynamicSharedMemorySize, GEMM_SMEM);
    cudaFuncSetAttribute(tc_gemm_kernel<1>,
                         cudaFuncAttributeMaxDynamicSharedMemorySize, GEMM_SMEM);
    cudaFuncSetAttribute(attn_mma_kernel,
                         cudaFuncAttributeMaxDynamicSharedMemorySize, ATTN_SMEM);

    // 1. prep
    prep_w_kernel<<<QKV_W, 128>>>(Wqkv, pWqh, pWql, 3 * C);
    prep_w_kernel<<<PRJ_W, 128>>>(Wprj, pWph, pWpl, C);
    prep_act_kernel<<<M, 128>>>(x, pxh, pxl, pxn2);

    // 2. bcos QKV projection -> bf16 split, head-major q/k/v (q pre-scaled)
    tc_gemm_kernel<1><<<dim3(QKV_W / BN, M / BM), 256, GEMM_SMEM>>>(
        pxh, pxl, pWqh, pWql, pxn2, nullptr, 0,
        pqh, pql, pkh, pkl, pvh, pvl);

    // 3. flash attention -> bf16 split ao + per-head partial norms
    attn_mma_kernel<<<dim3(N / 128, B * H), 256, ATTN_SMEM>>>(
        pqh, pql, pkh, pkl, pvh, pvl, paoh, paol, papart);

    // 4. bcos output projection -> d_out (norms summed from partials)
    tc_gemm_kernel<0><<<dim3(PRJ_W / BN, M / BM), 256, GEMM_SMEM>>>(
        paoh, paol, pWph, pWpl, papart, out, PRJ_O,
        nullptr, nullptr, nullptr, nullptr, nullptr, nullptr);
}

// round 9
// speedup vs baseline: 1.1191x; 1.1191x over previous
#include <cuda_runtime.h>
#include <cuda_bf16.h>
#include <cstdint>

namespace {
constexpr int B  = 2;
constexpr int N  = 2048;
constexpr int C  = 512;
constexpr int H  = 8;
constexpr int DH = 64;
constexpr int M  = B * N;          // 4096 tokens
constexpr int QKV_W = 3 * C * 2;   // 3072 weight rows
constexpr int PRJ_W = C * 2;       // 1024 weight rows
constexpr int PRJ_O = C;           // 512 fused outputs

constexpr int BM = 128;
constexpr int BN = 128;
constexpr int BK = 64;             // K chunk (bf16) = 128 bytes/row
constexpr int NC = 8;              // 512 / 64 chunks
// smem: 2 stages x (A{h,l} 32K + W{h,l} 32K) = 128 KB
constexpr int STAGE_BYTES = 65536;
constexpr int GEMM_SMEM  = 2 * STAGE_BYTES + 128;

constexpr int ATTN_SMEM = 2 * 16384 + 2 * 32768;  // Qh/Ql + 2 KV stages = 96 KB
}

// Scratch (device globals — no allocation allowed)
__device__ __nv_bfloat16 g_xh[(size_t)M * C];
__device__ __nv_bfloat16 g_xl[(size_t)M * C];
__device__ __nv_bfloat16 g_Wqh[(size_t)QKV_W * C];
__device__ __nv_bfloat16 g_Wql[(size_t)QKV_W * C];
__device__ __nv_bfloat16 g_Wph[(size_t)PRJ_W * C];
__device__ __nv_bfloat16 g_Wpl[(size_t)PRJ_W * C];
__device__ __nv_bfloat16 g_aoh[(size_t)M * C];
__device__ __nv_bfloat16 g_aol[(size_t)M * C];
// attention-ready qkv, head-major: [bh][n][64], hi/lo bf16
__device__ __nv_bfloat16 g_qh[(size_t)B * H * N * DH];
__device__ __nv_bfloat16 g_ql[(size_t)B * H * N * DH];
__device__ __nv_bfloat16 g_kh[(size_t)B * H * N * DH];
__device__ __nv_bfloat16 g_kl[(size_t)B * H * N * DH];
__device__ __nv_bfloat16 g_vh[(size_t)B * H * N * DH];
__device__ __nv_bfloat16 g_vl[(size_t)B * H * N * DH];
__device__ float g_xnorm2[M];             // sum of squares of x rows
__device__ float g_aopart[(size_t)H * M]; // per-head partial sumsq of ao rows

// ---------------------------------------------------------------------------
// PTX helpers (compute_103-safe: cp.async, ldmatrix, mma.sync bf16)
// ---------------------------------------------------------------------------
__device__ __forceinline__ uint32_t smem_u32(const void* p) {
    return (uint32_t)__cvta_generic_to_shared(p);
}
__device__ __forceinline__ void cp16(uint32_t s, const void* g) {
    asm volatile("cp.async.cg.shared.global [%0], [%1], 16;\n" :: "r"(s), "l"(g));
}
__device__ __forceinline__ uint32_t sw128(uint32_t off) {
    return off ^ ((off >> 3) & 0x70);
}
__device__ __forceinline__ void ldm_x4(uint32_t* r, uint32_t addr) {
    asm volatile("ldmatrix.sync.aligned.m8n8.x4.shared.b16 {%0,%1,%2,%3}, [%4];"
                 : "=r"(r[0]), "=r"(r[1]), "=r"(r[2]), "=r"(r[3]) : "r"(addr));
}
__device__ __forceinline__ void ldm_x4_t(uint32_t* r, uint32_t addr) {
    asm volatile("ldmatrix.sync.aligned.m8n8.x4.trans.shared.b16 {%0,%1,%2,%3}, [%4];"
                 : "=r"(r[0]), "=r"(r[1]), "=r"(r[2]), "=r"(r[3]) : "r"(addr));
}
__device__ __forceinline__ void mma16816(float* c, const uint32_t* a,
                                         const uint32_t* b) {
    asm volatile(
        "mma.sync.aligned.m16n8k16.row.col.f32.bf16.bf16.f32 "
        "{%0,%1,%2,%3}, {%4,%5,%6,%7}, {%8,%9}, {%0,%1,%2,%3};"
        : "+f"(c[0]), "+f"(c[1]), "+f"(c[2]), "+f"(c[3])
        : "r"(a[0]), "r"(a[1]), "r"(a[2]), "r"(a[3]), "r"(b[0]), "r"(b[1]));
}
__device__ __forceinline__ uint32_t packbf(float lo, float hi) {
    __nv_bfloat162 t = __floats2bfloat162_rn(lo, hi);
    return *(uint32_t*)&t;
}
__device__ __forceinline__ void split_pack(float lo, float hi,
                                           uint32_t& h, uint32_t& l) {
    h = packbf(lo, hi);
    __nv_bfloat162 hv = *(__nv_bfloat162*)&h;
    l = packbf(lo - __bfloat162float(hv.x), hi - __bfloat162float(hv.y));
}

// ---------------------------------------------------------------------------
// prep: per-row sum-of-squares + bf16 hi/lo split (x)
// ---------------------------------------------------------------------------
__global__ void prep_act_kernel(const float* __restrict__ A,
                                __nv_bfloat16* __restrict__ Ah,
                                __nv_bfloat16* __restrict__ Al,
                                float* __restrict__ norm2) {
    int r = blockIdx.x, t = threadIdx.x;
    float4 v = ((const float4*)(A + (size_t)r * C))[t];
    float s = v.x * v.x + v.y * v.y + v.z * v.z + v.w * v.w;
    #pragma unroll
    for (int o = 16; o; o >>= 1) s += __shfl_xor_sync(0xffffffffu, s, o);
    __shared__ float sm[4];
    if ((t & 31) == 0) sm[t >> 5] = s;
    __syncthreads();
    if (t == 0) norm2[r] = sm[0] + sm[1] + sm[2] + sm[3];
    float va[4] = {v.x, v.y, v.z, v.w};
    #pragma unroll
    for (int j = 0; j < 4; j++) {
        __nv_bfloat16 h = __float2bfloat16(va[j]);
        __nv_bfloat16 l = __float2bfloat16(va[j] - __bfloat162float(h));
        Ah[(size_t)r * C + t * 4 + j] = h;
        Al[(size_t)r * C + t * 4 + j] = l;
    }
}

// prep: normalize weight rows, maxout partners ADJACENT (o->2o, o+half->2o+1)
__global__ void prep_w_kernel(const float* __restrict__ W,
                              __nv_bfloat16* __restrict__ Dh,
                              __nv_bfloat16* __restrict__ Dl, int half) {
    int r = blockIdx.x, t = threadIdx.x;
    float4 v = ((const float4*)(W + (size_t)r * C))[t];
    float s = v.x * v.x + v.y * v.y + v.z * v.z + v.w * v.w;
    #pragma unroll
    for (int o = 16; o; o >>= 1) s += __shfl_xor_sync(0xffffffffu, s, o);
    __shared__ float sm[4];
    if ((t & 31) == 0) sm[t >> 5] = s;
    __syncthreads();
    float inv = rsqrtf(sm[0] + sm[1] + sm[2] + sm[3]);
    int dr = (r < half) ? 2 * r : 2 * (r - half) + 1;
    float va[4] = {v.x, v.y, v.z, v.w};
    #pragma unroll
    for (int j = 0; j < 4; j++) {
        float w = va[j] * inv;
        __nv_bfloat16 h = __float2bfloat16(w);
        __nv_bfloat16 l = __float2bfloat16(w - __bfloat162float(h));
        Dh[(size_t)dr * C + t * 4 + j] = h;
        Dl[(size_t)dr * C + t * 4 + j] = l;
    }
}

// ---------------------------------------------------------------------------
// mma.sync bcos GEMM (bf16x3), fragment-fused: per 64-K chunk load aH/aL/bH/bL
// fragments once, issue 48 MMAs (AhWh + AhWl + AlWh). 2-stage double buffer.
// MODE 0: proj — norms from 8 per-head partials, fp32 out.
// MODE 1: qkv — norms = x sumsq, bf16 split scatter head-major (q * 0.125).
// ---------------------------------------------------------------------------
template <int MODE>
__global__ __launch_bounds__(256, 1) void tc_gemm_kernel(
    const __nv_bfloat16* __restrict__ Ah, const __nv_bfloat16* __restrict__ Al,
    const __nv_bfloat16* __restrict__ Wh, const __nv_bfloat16* __restrict__ Wl,
    const float* __restrict__ norms, float* __restrict__ out, int nout,
    __nv_bfloat16* __restrict__ qh, __nv_bfloat16* __restrict__ ql,
    __nv_bfloat16* __restrict__ kh, __nv_bfloat16* __restrict__ kl,
    __nv_bfloat16* __restrict__ vh, __nv_bfloat16* __restrict__ vl)
{
    extern __shared__ char smem[];
    const uint32_t sbase = (smem_u32(smem) + 127) & ~127u;
    // stage layout: Ah[16K] | Al[16K] | Wh[16K] | Wl[16K]
    const int tid = threadIdx.x;
    const int lane = tid & 31;
    const int warp = tid >> 5;
    const int wm = warp >> 2;
    const int wn = warp & 3;
    const int bm = blockIdx.y * BM;
    const int bc = blockIdx.x * BN;

    auto load_chunk = [&](int k) {
        uint32_t st = sbase + (k & 1) * STAGE_BYTES;
        int k0 = k * BK;
        #pragma unroll
        for (int u = 0; u < 4; u++) {
            int c = tid + u * 256;
            int row = c >> 3, seg = c & 7;
            size_t goff = (size_t)row * C + k0 + seg * 8;
            uint32_t sw = sw128(row * 128 + seg * 16);
            cp16(st + sw,         Ah + (size_t)bm * C + goff);
            cp16(st + 16384 + sw, Al + (size_t)bm * C + goff);
            cp16(st + 32768 + sw, Wh + (size_t)bc * C + goff);
            cp16(st + 49152 + sw, Wl + (size_t)bc * C + goff);
        }
        asm volatile("cp.async.commit_group;\n");
    };

    float acc[4][4][4];
    #pragma unroll
    for (int i = 0; i < 4; i++)
        #pragma unroll
        for (int j = 0; j < 4; j++)
            #pragma unroll
            for (int q = 0; q < 4; q++) acc[i][j][q] = 0.f;

    load_chunk(0);
    load_chunk(1);

    for (int k = 0; k < NC; k++) {
        if (k + 2 <= NC) {
            asm volatile("cp.async.wait_group 1;\n" ::: "memory");
        } else {
            asm volatile("cp.async.wait_group 0;\n" ::: "memory");
        }
        __syncthreads();
        uint32_t st = sbase + (k & 1) * STAGE_BYTES;

        #pragma unroll
        for (int ks = 0; ks < 4; ks++) {
            uint32_t aHf[4][4], aLf[4][4], bHf[2][4], bLf[2][4];
            #pragma unroll
            for (int mt = 0; mt < 4; mt++) {
                int row = wm * 64 + mt * 16 + (lane & 15);
                int seg = ks * 2 + (lane >> 4);
                uint32_t off = sw128(row * 128 + seg * 16);
                ldm_x4(aHf[mt], st + off);
                ldm_x4(aLf[mt], st + 16384 + off);
            }
            #pragma unroll
            for (int p = 0; p < 2; p++) {
                int row = wn * 32 + p * 16 + (lane & 7) + ((lane >> 4) << 3);
                int seg = ks * 2 + ((lane >> 3) & 1);
                uint32_t off = sw128(row * 128 + seg * 16);
                ldm_x4(bHf[p], st + 32768 + off);
                ldm_x4(bLf[p], st + 49152 + off);
            }
            // 48 independent MMAs: AhWh, AhWl, AlWh
            #pragma unroll
            for (int mt = 0; mt < 4; mt++)
                #pragma unroll
                for (int nt = 0; nt < 4; nt++)
                    mma16816(acc[mt][nt], aHf[mt], &bHf[nt >> 1][(nt & 1) * 2]);
            #pragma unroll
            for (int mt = 0; mt < 4; mt++)
                #pragma unroll
                for (int nt = 0; nt < 4; nt++)
                    mma16816(acc[mt][nt], aHf[mt], &bLf[nt >> 1][(nt & 1) * 2]);
            #pragma unroll
            for (int mt = 0; mt < 4; mt++)
                #pragma unroll
                for (int nt = 0; nt < 4; nt++)
                    mma16816(acc[mt][nt], aLf[mt], &bHf[nt >> 1][(nt & 1) * 2]);
        }
        __syncthreads();
        if (k + 2 < NC) load_chunk(k + 2);
    }

    const float sc = rsqrtf((float)C);
    const int g = lane >> 2, tig = lane & 3;

    __nv_bfloat16 *dsth = nullptr, *dstl = nullptr;
    float qscale = 1.f;
    int hh = 0;
    if (MODE == 1) {
        int colbase = bc >> 1;
        int sect = colbase >> 9;
        hh = (colbase & 511) >> 6;
        if (sect == 0)      { dsth = qh; dstl = ql; qscale = 0.125f; }
        else if (sect == 1) { dsth = kh; dstl = kl; }
        else                { dsth = vh; dstl = vl; }
    }

    #pragma unroll
    for (int mt = 0; mt < 4; mt++) {
        int m0 = bm + wm * 64 + mt * 16;
        int r0 = m0 + g, r1 = m0 + g + 8;
        float inv0, inv1;
        if (MODE == 0) {
            float s0 = 0.f, s1 = 0.f;
            #pragma unroll
            for (int p = 0; p < H; p++) {
                s0 += norms[(size_t)p * M + r0];
                s1 += norms[(size_t)p * M + r1];
            }
            inv0 = sc * rsqrtf(s0);
            inv1 = sc * rsqrtf(s1);
        } else {
            inv0 = sc * rsqrtf(norms[r0]);
            inv1 = sc * rsqrtf(norms[r1]);
        }
        #pragma unroll
        for (int nt = 0; nt < 4; nt++) {
            float v0 = fmaxf(acc[mt][nt][0], acc[mt][nt][1]);
            v0 = v0 * fabsf(v0) * inv0;
            float v1 = fmaxf(acc[mt][nt][2], acc[mt][nt][3]);
            v1 = v1 * fabsf(v1) * inv1;
            if (MODE == 0) {
                int col = (bc >> 1) + wn * 16 + nt * 4 + tig;
                out[(size_t)r0 * nout + col] = v0;
                out[(size_t)r1 * nout + col] = v1;
            } else {
                int d = wn * 16 + nt * 4 + tig;
                v0 *= qscale; v1 *= qscale;
                __nv_bfloat16 h0 = __float2bfloat16(v0);
                __nv_bfloat16 h1 = __float2bfloat16(v1);
                size_t i0 = ((size_t)(((r0 >> 11) << 3) + hh) * N + (r0 & 2047)) * DH + d;
                size_t i1 = ((size_t)(((r1 >> 11) << 3) + hh) * N + (r1 & 2047)) * DH + d;
                dsth[i0] = h0; dstl[i0] = __float2bfloat16(v0 - __bfloat162float(h0));
                dsth[i1] = h1; dstl[i1] = __float2bfloat16(v1 - __bfloat162float(h1));
            }
        }
    }
}

// ---------------------------------------------------------------------------
// Flash attention, mma.sync bf16 split (unchanged from R7 — known good).
// ---------------------------------------------------------------------------
__global__ __launch_bounds__(256, 2) void attn_mma_kernel(
    const __nv_bfloat16* __restrict__ qh, const __nv_bfloat16* __restrict__ ql,
    const __nv_bfloat16* __restrict__ kh, const __nv_bfloat16* __restrict__ kl,
    const __nv_bfloat16* __restrict__ vh, const __nv_bfloat16* __restrict__ vl,
    __nv_bfloat16* __restrict__ aoh, __nv_bfloat16* __restrict__ aol,
    float* __restrict__ aopart)
{
    extern __shared__ char smem[];
    const uint32_t sQh = smem_u32(smem);
    const uint32_t sQl = sQh + 16384;
    const uint32_t sKV = sQl + 16384;       // 2 stages x {Kh,Kl,Vh,Vl} x 8KB

    const int bh = blockIdx.y;
    const int q0 = blockIdx.x * 128;
    const int tid = threadIdx.x;
    const int lane = tid & 31;
    const int warp = tid >> 5;
    const int g = lane >> 2, tig = lane & 3;
    const int wr = warp * 16;
    const size_t tok0 = (size_t)bh * N;

    {
        const __nv_bfloat16* srcs[2] = {qh, ql};
        #pragma unroll
        for (int u = 0; u < 8; u++) {
            const __nv_bfloat16* src = srcs[u >> 2];
            uint32_t dst = (u >> 2) ? sQl : sQh;
            int c = (u & 3) * 256 + tid;
            int row = c >> 3, seg = c & 7;
            cp16(dst + sw128(row * 128 + seg * 16),
                 src + (tok0 + q0 + row) * DH + seg * 8);
        }
    }
    auto load_kv = [&](int t) {
        int kv0 = t * 64;
        uint32_t sbase = sKV + (t & 1) * 32768;
        const __nv_bfloat16* srcs[4] = {kh, kl, vh, vl};
        #pragma unroll
        for (int u = 0; u < 8; u++) {
            const __nv_bfloat16* src = srcs[u >> 1];
            uint32_t dst = sbase + (u >> 1) * 8192;
            int c = (u & 1) * 256 + tid;
            int row = c >> 3, seg = c & 7;
            cp16(dst + sw128(row * 128 + seg * 16),
                 src + (tok0 + kv0 + row) * DH + seg * 8);
        }
        asm volatile("cp.async.commit_group;\n");
    };
    load_kv(0);   // group 0 = Q + KV0

    float o[8][4];
    #pragma unroll
    for (int nt = 0; nt < 8; nt++)
        #pragma unroll
        for (int q = 0; q < 4; q++) o[nt][q] = 0.f;
    float m0r = -1e30f, m1r = -1e30f, l0r = 0.f, l1r = 0.f;

    const int NKV = N / 64;
    for (int t = 0; t < NKV; t++) {
        if (t + 1 < NKV) {
            load_kv(t + 1);
            asm volatile("cp.async.wait_group 1;\n" ::: "memory");
        } else {
            asm volatile("cp.async.wait_group 0;\n" ::: "memory");
        }
        __syncthreads();
        uint32_t sK = sKV + (t & 1) * 32768;       // Kh
        uint32_t sKl = sK + 8192;
        uint32_t sV = sK + 16384;                  // Vh
        uint32_t sVl = sK + 24576;

        // ---- S = Q K^T (3 split terms)
        float s[8][4];
        #pragma unroll
        for (int nt = 0; nt < 8; nt++)
            #pragma unroll
            for (int q = 0; q < 4; q++) s[nt][q] = 0.f;

        #pragma unroll
        for (int kt = 0; kt < 4; kt++) {
            uint32_t aH[4], aL[4];
            {
                int row = wr + (lane & 15);
                int seg = kt * 2 + (lane >> 4);
                uint32_t off = sw128(row * 128 + seg * 16);
                ldm_x4(aH, sQh + off);
                ldm_x4(aL, sQl + off);
            }
            #pragma unroll
            for (int bn = 0; bn < 4; bn++) {
                int row = bn * 16 + (lane & 7) + ((lane >> 4) << 3);
                int seg = kt * 2 + ((lane >> 3) & 1);
                uint32_t off = sw128(row * 128 + seg * 16);
                uint32_t bH[4], bL[4];
                ldm_x4(bH, sK + off);
                ldm_x4(bL, sKl + off);
                #pragma unroll
                for (int sub = 0; sub < 2; sub++) {
                    int nt = bn * 2 + sub;
                    mma16816(s[nt], aH, &bH[sub * 2]);
                    mma16816(s[nt], aL, &bH[sub * 2]);
                    mma16816(s[nt], aH, &bL[sub * 2]);
                }
            }
        }

        // ---- online softmax (rows g and g+8, warp-local over tig lanes)
        float tm0 = -1e30f, tm1 = -1e30f;
        #pragma unroll
        for (int nt = 0; nt < 8; nt++) {
            tm0 = fmaxf(tm0, fmaxf(s[nt][0], s[nt][1]));
            tm1 = fmaxf(tm1, fmaxf(s[nt][2], s[nt][3]));
        }
        tm0 = fmaxf(tm0, __shfl_xor_sync(0xffffffffu, tm0, 1));
        tm0 = fmaxf(tm0, __shfl_xor_sync(0xffffffffu, tm0, 2));
        tm1 = fmaxf(tm1, __shfl_xor_sync(0xffffffffu, tm1, 1));
        tm1 = fmaxf(tm1, __shfl_xor_sync(0xffffffffu, tm1, 2));
        float mn0 = fmaxf(m0r, tm0), mn1 = fmaxf(m1r, tm1);
        float rs0 = __expf(m0r - mn0), rs1 = __expf(m1r - mn1);
        float ts0 = 0.f, ts1 = 0.f;
        #pragma unroll
        for (int nt = 0; nt < 8; nt++) {
            s[nt][0] = __expf(s[nt][0] - mn0); ts0 += s[nt][0];
            s[nt][1] = __expf(s[nt][1] - mn0); ts0 += s[nt][1];
            s[nt][2] = __expf(s[nt][2] - mn1); ts1 += s[nt][2];
            s[nt][3] = __expf(s[nt][3] - mn1); ts1 += s[nt][3];
        }
        ts0 += __shfl_xor_sync(0xffffffffu, ts0, 1);
        ts0 += __shfl_xor_sync(0xffffffffu, ts0, 2);
        ts1 += __shfl_xor_sync(0xffffffffu, ts1, 1);
        ts1 += __shfl_xor_sync(0xffffffffu, ts1, 2);
        l0r = l0r * rs0 + ts0; m0r = mn0;
        l1r = l1r * rs1 + ts1; m1r = mn1;
        #pragma unroll
        for (int nt = 0; nt < 8; nt++) {
            o[nt][0] *= rs0; o[nt][1] *= rs0;
            o[nt][2] *= rs1; o[nt][3] *= rs1;
        }

        // ---- P fragments (A-operand layout), hi/lo split in registers
        uint32_t ph[4][4], pl[4][4];
        #pragma unroll
        for (int kt = 0; kt < 4; kt++) {
            split_pack(s[2 * kt][0],     s[2 * kt][1],     ph[kt][0], pl[kt][0]);
            split_pack(s[2 * kt][2],     s[2 * kt][3],     ph[kt][1], pl[kt][1]);
            split_pack(s[2 * kt + 1][0], s[2 * kt + 1][1], ph[kt][2], pl[kt][2]);
            split_pack(s[2 * kt + 1][2], s[2 * kt + 1][3], ph[kt][3], pl[kt][3]);
        }

        // ---- O += P V  (PhVh + PlVh + PhVl), V frags via ldmatrix.trans
        #pragma unroll
        for (int kt = 0; kt < 4; kt++) {
            #pragma unroll
            for (int bn = 0; bn < 4; bn++) {
                int mat = lane >> 3, i = lane & 7;
                int row = kt * 16 + (mat & 1) * 8 + i;
                int coloff = (bn * 16 + (mat >> 1) * 8) * 2;
                uint32_t off = sw128(row * 128 + coloff);
                uint32_t bH[4], bL[4];
                ldm_x4_t(bH, sV + off);
                ldm_x4_t(bL, sVl + off);
                #pragma unroll
                for (int sub = 0; sub < 2; sub++) {
                    int nt = bn * 2 + sub;
                    mma16816(o[nt], ph[kt], &bH[sub * 2]);
                    mma16816(o[nt], pl[kt], &bH[sub * 2]);
                    mma16816(o[nt], ph[kt], &bL[sub * 2]);
                }
            }
        }
        __syncthreads();
    }

    // ---- epilogue: /l, bf16 hi/lo split, partial sumsq per (head,row)
    const int b = bh >> 3;
    const int h = bh & 7;
    const int hoff = h * DH;
    const float inv0 = 1.f / l0r, inv1 = 1.f / l1r;
    const int row0 = q0 + wr + g;
    const size_t base0 = (size_t)(b * N + row0) * C + hoff + 2 * tig;
    const size_t base1 = (size_t)(b * N + row0 + 8) * C + hoff + 2 * tig;
    float ss0 = 0.f, ss1 = 0.f;
    #pragma unroll
    for (int nt = 0; nt < 8; nt++) {
        float a0 = o[nt][0] * inv0, a1 = o[nt][1] * inv0;
        float b0 = o[nt][2] * inv1, b1 = o[nt][3] * inv1;
        ss0 += a0 * a0 + a1 * a1;
        ss1 += b0 * b0 + b1 * b1;
        uint32_t h0, l0, h1, l1;
        split_pack(a0, a1, h0, l0);
        split_pack(b0, b1, h1, l1);
        *(uint32_t*)(aoh + base0 + nt * 8) = h0;
        *(uint32_t*)(aol + base0 + nt * 8) = l0;
        *(uint32_t*)(aoh + base1 + nt * 8) = h1;
        *(uint32_t*)(aol + base1 + nt * 8) = l1;
    }
    ss0 += __shfl_xor_sync(0xffffffffu, ss0, 1);
    ss0 += __shfl_xor_sync(0xffffffffu, ss0, 2);
    ss1 += __shfl_xor_sync(0xffffffffu, ss1, 1);
    ss1 += __shfl_xor_sync(0xffffffffu, ss1, 2);
    if (tig == 0) {
        aopart[(size_t)h * M + b * N + row0]     = ss0;
        aopart[(size_t)h * M + b * N + row0 + 8] = ss1;
    }
}

// ---------------------------------------------------------------------------

extern "C" void kernel_launch(void* const* d_in, const int* in_sizes, int n_in,
                              void* d_out, int out_size) {
    (void)in_sizes; (void)n_in; (void)out_size;
    const float* x    = (const float*)d_in[0];
    const float* Wqkv = (const float*)d_in[1];
    const float* Wprj = (const float*)d_in[2];
    float* out = (float*)d_out;

    __nv_bfloat16 *pxh, *pxl, *pWqh, *pWql, *pWph, *pWpl, *paoh, *paol;
    __nv_bfloat16 *pqh, *pql, *pkh, *pkl, *pvh, *pvl;
    float *pxn2, *papart;
    cudaGetSymbolAddress((void**)&pxh,  g_xh);
    cudaGetSymbolAddress((void**)&pxl,  g_xl);
    cudaGetSymbolAddress((void**)&pWqh, g_Wqh);
    cudaGetSymbolAddress((void**)&pWql, g_Wql);
    cudaGetSymbolAddress((void**)&pWph, g_Wph);
    cudaGetSymbolAddress((void**)&pWpl, g_Wpl);
    cudaGetSymbolAddress((void**)&paoh, g_aoh);
    cudaGetSymbolAddress((void**)&paol, g_aol);
    cudaGetSymbolAddress((void**)&pqh,  g_qh);
    cudaGetSymbolAddress((void**)&pql,  g_ql);
    cudaGetSymbolAddress((void**)&pkh,  g_kh);
    cudaGetSymbolAddress((void**)&pkl,  g_kl);
    cudaGetSymbolAddress((void**)&pvh,  g_vh);
    cudaGetSymbolAddress((void**)&pvl,  g_vl);
    cudaGetSymbolAddress((void**)&pxn2, g_xnorm2);
    cudaGetSymbolAddress((void**)&papart, g_aopart);

    cudaFuncSetAttribute(tc_gemm_kernel<0>,
                         cudaFuncAttributeMaxDynamicSharedMemorySize, GEMM_SMEM);
    cudaFuncSetAttribute(tc_gemm_kernel<1>,
                         cudaFuncAttributeMaxDynamicSharedMemorySize, GEMM_SMEM);
    cudaFuncSetAttribute(attn_mma_kernel,
                         cudaFuncAttributeMaxDynamicSharedMemorySize, ATTN_SMEM);

    // 1. prep
    prep_w_kernel<<<QKV_W, 128>>>(Wqkv, pWqh, pWql, 3 * C);
    prep_w_kernel<<<PRJ_W, 128>>>(Wprj, pWph, pWpl, C);
    prep_act_kernel<<<M, 128>>>(x, pxh, pxl, pxn2);

    // 2. bcos QKV projection -> bf16 split, head-major q/k/v (q pre-scaled)
    tc_gemm_kernel<1><<<dim3(QKV_W / BN, M / BM), 256, GEMM_SMEM>>>(
        pxh, pxl, pWqh, pWql, pxn2, nullptr, 0,
        pqh, pql, pkh, pkl, pvh, pvl);

    // 3. flash attention -> bf16 split ao + per-head partial norms
    attn_mma_kernel<<<dim3(N / 128, B * H), 256, ATTN_SMEM>>>(
        pqh, pql, pkh, pkl, pvh, pvl, paoh, paol, papart);

    // 4. bcos output projection -> d_out (norms summed from partials)
    tc_gemm_kernel<0><<<dim3(PRJ_W / BN, M / BM), 256, GEMM_SMEM>>>(
        paoh, paol, pWph, pWpl, papart, out, PRJ_O,
        nullptr, nullptr, nullptr, nullptr, nullptr, nullptr);
}

// round 10
// speedup vs baseline: 1.5382x; 1.3745x over previous
#include <cuda_runtime.h>
#include <cuda_bf16.h>
#include <cstdint>

namespace {
constexpr int B  = 2;
constexpr int N  = 2048;
constexpr int C  = 512;
constexpr int H  = 8;
constexpr int DH = 64;
constexpr int M  = B * N;          // 4096 tokens
constexpr int QKV_W = 3 * C * 2;   // 3072 weight rows
constexpr int PRJ_W = C * 2;       // 1024 weight rows
constexpr int PRJ_O = C;           // 512 fused outputs

constexpr int BM = 128;
constexpr int BN = 128;
constexpr int BK = 64;             // K tile (bf16) = 128 bytes/row
constexpr int NT = 24;             // 3 split phases * (512/64)
constexpr int TILE_BYTES = BM * 128;
constexpr int BUF_BYTES  = 2 * TILE_BYTES;        // A+B per stage (32 KB)
constexpr int GEMM_SMEM  = 3 * BUF_BYTES + 128;   // 3-stage pipeline

// attn: Q 16K + 2 KV stages x (K 8K + V 8K) = 48 KB
constexpr int ATTN_SMEM = 16384 + 2 * 16384;
}

// Scratch (device globals — no allocation allowed)
__device__ __nv_bfloat16 g_xh[(size_t)M * C];
__device__ __nv_bfloat16 g_xl[(size_t)M * C];
__device__ __nv_bfloat16 g_Wqh[(size_t)QKV_W * C];
__device__ __nv_bfloat16 g_Wql[(size_t)QKV_W * C];
__device__ __nv_bfloat16 g_Wph[(size_t)PRJ_W * C];
__device__ __nv_bfloat16 g_Wpl[(size_t)PRJ_W * C];
__device__ __nv_bfloat16 g_aoh[(size_t)M * C];
__device__ __nv_bfloat16 g_aol[(size_t)M * C];
// attention-ready qkv, head-major: [bh][n][64], plain bf16
__device__ __nv_bfloat16 g_q[(size_t)B * H * N * DH];
__device__ __nv_bfloat16 g_k[(size_t)B * H * N * DH];
__device__ __nv_bfloat16 g_v[(size_t)B * H * N * DH];
__device__ float g_xnorm2[M];             // sum of squares of x rows
__device__ float g_aopart[(size_t)H * M]; // per-head partial sumsq of ao rows

// ---------------------------------------------------------------------------
// PTX helpers (compute_103-safe: cp.async, ldmatrix, mma.sync bf16)
// ---------------------------------------------------------------------------
__device__ __forceinline__ uint32_t smem_u32(const void* p) {
    return (uint32_t)__cvta_generic_to_shared(p);
}
__device__ __forceinline__ void cp16(uint32_t s, const void* g) {
    asm volatile("cp.async.cg.shared.global [%0], [%1], 16;\n" :: "r"(s), "l"(g));
}
__device__ __forceinline__ uint32_t sw128(uint32_t off) {
    return off ^ ((off >> 3) & 0x70);
}
__device__ __forceinline__ void ldm_x4(uint32_t* r, uint32_t addr) {
    asm volatile("ldmatrix.sync.aligned.m8n8.x4.shared.b16 {%0,%1,%2,%3}, [%4];"
                 : "=r"(r[0]), "=r"(r[1]), "=r"(r[2]), "=r"(r[3]) : "r"(addr));
}
__device__ __forceinline__ void ldm_x4_t(uint32_t* r, uint32_t addr) {
    asm volatile("ldmatrix.sync.aligned.m8n8.x4.trans.shared.b16 {%0,%1,%2,%3}, [%4];"
                 : "=r"(r[0]), "=r"(r[1]), "=r"(r[2]), "=r"(r[3]) : "r"(addr));
}
__device__ __forceinline__ void mma16816(float* c, const uint32_t* a,
                                         const uint32_t* b) {
    asm volatile(
        "mma.sync.aligned.m16n8k16.row.col.f32.bf16.bf16.f32 "
        "{%0,%1,%2,%3}, {%4,%5,%6,%7}, {%8,%9}, {%0,%1,%2,%3};"
        : "+f"(c[0]), "+f"(c[1]), "+f"(c[2]), "+f"(c[3])
        : "r"(a[0]), "r"(a[1]), "r"(a[2]), "r"(a[3]), "r"(b[0]), "r"(b[1]));
}
__device__ __forceinline__ uint32_t packbf(float lo, float hi) {
    __nv_bfloat162 t = __floats2bfloat162_rn(lo, hi);
    return *(uint32_t*)&t;
}
__device__ __forceinline__ void split_pack(float lo, float hi,
                                           uint32_t& h, uint32_t& l) {
    h = packbf(lo, hi);
    __nv_bfloat162 hv = *(__nv_bfloat162*)&h;
    l = packbf(lo - __bfloat162float(hv.x), hi - __bfloat162float(hv.y));
}

// ---------------------------------------------------------------------------
// prep: per-row sum-of-squares + bf16 hi/lo split (x)
// ---------------------------------------------------------------------------
__global__ void prep_act_kernel(const float* __restrict__ A,
                                __nv_bfloat16* __restrict__ Ah,
                                __nv_bfloat16* __restrict__ Al,
                                float* __restrict__ norm2) {
    int r = blockIdx.x, t = threadIdx.x;
    float4 v = ((const float4*)(A + (size_t)r * C))[t];
    float s = v.x * v.x + v.y * v.y + v.z * v.z + v.w * v.w;
    #pragma unroll
    for (int o = 16; o; o >>= 1) s += __shfl_xor_sync(0xffffffffu, s, o);
    __shared__ float sm[4];
    if ((t & 31) == 0) sm[t >> 5] = s;
    __syncthreads();
    if (t == 0) norm2[r] = sm[0] + sm[1] + sm[2] + sm[3];
    float va[4] = {v.x, v.y, v.z, v.w};
    #pragma unroll
    for (int j = 0; j < 4; j++) {
        __nv_bfloat16 h = __float2bfloat16(va[j]);
        __nv_bfloat16 l = __float2bfloat16(va[j] - __bfloat162float(h));
        Ah[(size_t)r * C + t * 4 + j] = h;
        Al[(size_t)r * C + t * 4 + j] = l;
    }
}

// prep: normalize weight rows, maxout partners ADJACENT (o->2o, o+half->2o+1)
__global__ void prep_w_kernel(const float* __restrict__ W,
                              __nv_bfloat16* __restrict__ Dh,
                              __nv_bfloat16* __restrict__ Dl, int half) {
    int r = blockIdx.x, t = threadIdx.x;
    float4 v = ((const float4*)(W + (size_t)r * C))[t];
    float s = v.x * v.x + v.y * v.y + v.z * v.z + v.w * v.w;
    #pragma unroll
    for (int o = 16; o; o >>= 1) s += __shfl_xor_sync(0xffffffffu, s, o);
    __shared__ float sm[4];
    if ((t & 31) == 0) sm[t >> 5] = s;
    __syncthreads();
    float inv = rsqrtf(sm[0] + sm[1] + sm[2] + sm[3]);
    int dr = (r < half) ? 2 * r : 2 * (r - half) + 1;
    float va[4] = {v.x, v.y, v.z, v.w};
    #pragma unroll
    for (int j = 0; j < 4; j++) {
        float w = va[j] * inv;
        __nv_bfloat16 h = __float2bfloat16(w);
        __nv_bfloat16 l = __float2bfloat16(w - __bfloat162float(h));
        Dh[(size_t)dr * C + t * 4 + j] = h;
        Dl[(size_t)dr * C + t * 4 + j] = l;
    }
}

// ---------------------------------------------------------------------------
// mma.sync bcos GEMM (bf16x3), 3-stage cp.async pipeline (R7 structure).
// MODE 0: proj — norms from 8 per-head partials, fp32 out.
// MODE 1: qkv — norms = x sumsq, plain-bf16 scatter head-major (q * 0.125).
// ---------------------------------------------------------------------------
template <int MODE>
__global__ __launch_bounds__(256, 2) void tc_gemm_kernel(
    const __nv_bfloat16* __restrict__ Ah, const __nv_bfloat16* __restrict__ Al,
    const __nv_bfloat16* __restrict__ Wh, const __nv_bfloat16* __restrict__ Wl,
    const float* __restrict__ norms, float* __restrict__ out, int nout,
    __nv_bfloat16* __restrict__ q, __nv_bfloat16* __restrict__ k,
    __nv_bfloat16* __restrict__ v)
{
    extern __shared__ char smem[];
    const uint32_t tiles = (smem_u32(smem) + 127) & ~127u;
    const int tid = threadIdx.x;
    const int lane = tid & 31;
    const int warp = tid >> 5;
    const int wm = warp >> 2;
    const int wn = warp & 3;
    const int bm = blockIdx.y * BM;
    const int bc = blockIdx.x * BN;

    auto load_tile = [&](int t) {
        int phase = t >> 3;
        int k0 = (t & 7) * BK;
        const __nv_bfloat16* As = (phase == 2) ? Al : Ah;
        const __nv_bfloat16* Ws = (phase == 1) ? Wl : Wh;
        uint32_t ab = tiles + (t % 3) * BUF_BYTES;
        uint32_t bb = ab + TILE_BYTES;
        #pragma unroll
        for (int u = 0; u < 4; u++) {
            int c = tid + u * 256;
            int row = c >> 3, seg = c & 7;
            uint32_t sw = sw128(row * 128 + seg * 16);
            cp16(ab + sw, As + (size_t)(bm + row) * C + k0 + seg * 8);
            cp16(bb + sw, Ws + (size_t)(bc + row) * C + k0 + seg * 8);
        }
        asm volatile("cp.async.commit_group;\n");
    };

    float acc[4][4][4];
    #pragma unroll
    for (int i = 0; i < 4; i++)
        #pragma unroll
        for (int j = 0; j < 4; j++)
            #pragma unroll
            for (int qq = 0; qq < 4; qq++) acc[i][j][qq] = 0.f;

    load_tile(0);
    load_tile(1);

    for (int t = 0; t < NT; t++) {
        asm volatile("cp.async.wait_group 1;\n" ::: "memory");
        __syncthreads();
        if (t + 2 < NT) load_tile(t + 2);

        uint32_t ab = tiles + (t % 3) * BUF_BYTES;
        uint32_t bb = ab + TILE_BYTES;

        #pragma unroll
        for (int ks = 0; ks < 4; ks++) {
            uint32_t afrag[4][4], bfrag[2][4];
            #pragma unroll
            for (int mt = 0; mt < 4; mt++) {
                int row = wm * 64 + mt * 16 + (lane & 15);
                int seg = ks * 2 + (lane >> 4);
                ldm_x4(afrag[mt], ab + sw128(row * 128 + seg * 16));
            }
            #pragma unroll
            for (int p = 0; p < 2; p++) {
                int row = wn * 32 + p * 16 + (lane & 7) + ((lane >> 4) << 3);
                int seg = ks * 2 + ((lane >> 3) & 1);
                ldm_x4(bfrag[p], bb + sw128(row * 128 + seg * 16));
            }
            #pragma unroll
            for (int mt = 0; mt < 4; mt++)
                #pragma unroll
                for (int nt = 0; nt < 4; nt++)
                    mma16816(acc[mt][nt], afrag[mt], &bfrag[nt >> 1][(nt & 1) * 2]);
        }
    }

    const float sc = rsqrtf((float)C);
    const int g = lane >> 2, tig = lane & 3;

    __nv_bfloat16* dst = nullptr;
    float qscale = 1.f;
    int hh = 0;
    if (MODE == 1) {
        int colbase = bc >> 1;
        int sect = colbase >> 9;
        hh = (colbase & 511) >> 6;
        if (sect == 0)      { dst = q; qscale = 0.125f; }
        else if (sect == 1) { dst = k; }
        else                { dst = v; }
    }

    #pragma unroll
    for (int mt = 0; mt < 4; mt++) {
        int m0 = bm + wm * 64 + mt * 16;
        int r0 = m0 + g, r1 = m0 + g + 8;
        float inv0, inv1;
        if (MODE == 0) {
            float s0 = 0.f, s1 = 0.f;
            #pragma unroll
            for (int p = 0; p < H; p++) {
                s0 += norms[(size_t)p * M + r0];
                s1 += norms[(size_t)p * M + r1];
            }
            inv0 = sc * rsqrtf(s0);
            inv1 = sc * rsqrtf(s1);
        } else {
            inv0 = sc * rsqrtf(norms[r0]);
            inv1 = sc * rsqrtf(norms[r1]);
        }
        #pragma unroll
        for (int nt = 0; nt < 4; nt++) {
            float v0 = fmaxf(acc[mt][nt][0], acc[mt][nt][1]);
            v0 = v0 * fabsf(v0) * inv0;
            float v1 = fmaxf(acc[mt][nt][2], acc[mt][nt][3]);
            v1 = v1 * fabsf(v1) * inv1;
            if (MODE == 0) {
                int col = (bc >> 1) + wn * 16 + nt * 4 + tig;
                out[(size_t)r0 * nout + col] = v0;
                out[(size_t)r1 * nout + col] = v1;
            } else {
                int d = wn * 16 + nt * 4 + tig;
                size_t i0 = ((size_t)(((r0 >> 11) << 3) + hh) * N + (r0 & 2047)) * DH + d;
                size_t i1 = ((size_t)(((r1 >> 11) << 3) + hh) * N + (r1 & 2047)) * DH + d;
                dst[i0] = __float2bfloat16(v0 * qscale);
                dst[i1] = __float2bfloat16(v1 * qscale);
            }
        }
    }
}

// ---------------------------------------------------------------------------
// Flash attention, plain bf16 mma.sync (single-term QK and PV — logits are
// tiny and softmax averaging damps rounding, so the split is not needed).
// Block = 128 q-rows of one (b,h). Epilogue writes bf16 hi/lo ao + partials.
// ---------------------------------------------------------------------------
__global__ __launch_bounds__(256, 2) void attn_mma_kernel(
    const __nv_bfloat16* __restrict__ q, const __nv_bfloat16* __restrict__ k,
    const __nv_bfloat16* __restrict__ v,
    __nv_bfloat16* __restrict__ aoh, __nv_bfloat16* __restrict__ aol,
    float* __restrict__ aopart)
{
    extern __shared__ char smem[];
    const uint32_t sQ  = smem_u32(smem);
    const uint32_t sKV = sQ + 16384;        // 2 stages x {K 8K, V 8K}

    const int bh = blockIdx.y;
    const int q0 = blockIdx.x * 128;
    const int tid = threadIdx.x;
    const int lane = tid & 31;
    const int warp = tid >> 5;
    const int g = lane >> 2, tig = lane & 3;
    const int wr = warp * 16;
    const size_t tok0 = (size_t)bh * N;

    // Q tile: 128 rows x 128B (bundled into load_kv(0)'s commit group)
    #pragma unroll
    for (int u = 0; u < 4; u++) {
        int c = u * 256 + tid;
        int row = c >> 3, seg = c & 7;
        cp16(sQ + sw128(row * 128 + seg * 16),
             q + (tok0 + q0 + row) * DH + seg * 8);
    }
    auto load_kv = [&](int t) {
        int kv0 = t * 64;
        uint32_t sbase = sKV + (t & 1) * 16384;
        #pragma unroll
        for (int u = 0; u < 4; u++) {
            const __nv_bfloat16* src = (u >> 1) ? v : k;
            uint32_t dst = sbase + (u >> 1) * 8192;
            int c = (u & 1) * 256 + tid;
            int row = c >> 3, seg = c & 7;
            cp16(dst + sw128(row * 128 + seg * 16),
                 src + (tok0 + kv0 + row) * DH + seg * 8);
        }
        asm volatile("cp.async.commit_group;\n");
    };
    load_kv(0);

    float o[8][4];
    #pragma unroll
    for (int nt = 0; nt < 8; nt++)
        #pragma unroll
        for (int qq = 0; qq < 4; qq++) o[nt][qq] = 0.f;
    float m0r = -1e30f, m1r = -1e30f, l0r = 0.f, l1r = 0.f;

    const int NKV = N / 64;
    for (int t = 0; t < NKV; t++) {
        if (t + 1 < NKV) {
            load_kv(t + 1);
            asm volatile("cp.async.wait_group 1;\n" ::: "memory");
        } else {
            asm volatile("cp.async.wait_group 0;\n" ::: "memory");
        }
        __syncthreads();
        uint32_t sK = sKV + (t & 1) * 16384;
        uint32_t sV = sK + 8192;

        // ---- S = Q K^T (single term)
        float s[8][4];
        #pragma unroll
        for (int nt = 0; nt < 8; nt++)
            #pragma unroll
            for (int qq = 0; qq < 4; qq++) s[nt][qq] = 0.f;

        #pragma unroll
        for (int kt = 0; kt < 4; kt++) {
            uint32_t aH[4];
            {
                int row = wr + (lane & 15);
                int seg = kt * 2 + (lane >> 4);
                ldm_x4(aH, sQ + sw128(row * 128 + seg * 16));
            }
            #pragma unroll
            for (int bn = 0; bn < 4; bn++) {
                int row = bn * 16 + (lane & 7) + ((lane >> 4) << 3);
                int seg = kt * 2 + ((lane >> 3) & 1);
                uint32_t bH[4];
                ldm_x4(bH, sK + sw128(row * 128 + seg * 16));
                #pragma unroll
                for (int sub = 0; sub < 2; sub++)
                    mma16816(s[bn * 2 + sub], aH, &bH[sub * 2]);
            }
        }

        // ---- online softmax (rows g and g+8, warp-local over tig lanes)
        float tm0 = -1e30f, tm1 = -1e30f;
        #pragma unroll
        for (int nt = 0; nt < 8; nt++) {
            tm0 = fmaxf(tm0, fmaxf(s[nt][0], s[nt][1]));
            tm1 = fmaxf(tm1, fmaxf(s[nt][2], s[nt][3]));
        }
        tm0 = fmaxf(tm0, __shfl_xor_sync(0xffffffffu, tm0, 1));
        tm0 = fmaxf(tm0, __shfl_xor_sync(0xffffffffu, tm0, 2));
        tm1 = fmaxf(tm1, __shfl_xor_sync(0xffffffffu, tm1, 1));
        tm1 = fmaxf(tm1, __shfl_xor_sync(0xffffffffu, tm1, 2));
        float mn0 = fmaxf(m0r, tm0), mn1 = fmaxf(m1r, tm1);
        float rs0 = __expf(m0r - mn0), rs1 = __expf(m1r - mn1);
        float ts0 = 0.f, ts1 = 0.f;
        #pragma unroll
        for (int nt = 0; nt < 8; nt++) {
            s[nt][0] = __expf(s[nt][0] - mn0); ts0 += s[nt][0];
            s[nt][1] = __expf(s[nt][1] - mn0); ts0 += s[nt][1];
            s[nt][2] = __expf(s[nt][2] - mn1); ts1 += s[nt][2];
            s[nt][3] = __expf(s[nt][3] - mn1); ts1 += s[nt][3];
        }
        ts0 += __shfl_xor_sync(0xffffffffu, ts0, 1);
        ts0 += __shfl_xor_sync(0xffffffffu, ts0, 2);
        ts1 += __shfl_xor_sync(0xffffffffu, ts1, 1);
        ts1 += __shfl_xor_sync(0xffffffffu, ts1, 2);
        l0r = l0r * rs0 + ts0; m0r = mn0;
        l1r = l1r * rs1 + ts1; m1r = mn1;
        #pragma unroll
        for (int nt = 0; nt < 8; nt++) {
            o[nt][0] *= rs0; o[nt][1] *= rs0;
            o[nt][2] *= rs1; o[nt][3] *= rs1;
        }

        // ---- P fragments (A-operand layout), plain bf16
        uint32_t ph[4][4];
        #pragma unroll
        for (int kt = 0; kt < 4; kt++) {
            ph[kt][0] = packbf(s[2 * kt][0],     s[2 * kt][1]);
            ph[kt][1] = packbf(s[2 * kt][2],     s[2 * kt][3]);
            ph[kt][2] = packbf(s[2 * kt + 1][0], s[2 * kt + 1][1]);
            ph[kt][3] = packbf(s[2 * kt + 1][2], s[2 * kt + 1][3]);
        }

        // ---- O += P V (single term), V frags via ldmatrix.trans
        #pragma unroll
        for (int kt = 0; kt < 4; kt++) {
            #pragma unroll
            for (int bn = 0; bn < 4; bn++) {
                int mat = lane >> 3, i = lane & 7;
                int row = kt * 16 + (mat & 1) * 8 + i;
                int coloff = (bn * 16 + (mat >> 1) * 8) * 2;
                uint32_t bH[4];
                ldm_x4_t(bH, sV + sw128(row * 128 + coloff));
                #pragma unroll
                for (int sub = 0; sub < 2; sub++)
                    mma16816(o[bn * 2 + sub], ph[kt], &bH[sub * 2]);
            }
        }
        __syncthreads();
    }

    // ---- epilogue: /l, bf16 hi/lo split, partial sumsq per (head,row)
    const int b = bh >> 3;
    const int h = bh & 7;
    const int hoff = h * DH;
    const float inv0 = 1.f / l0r, inv1 = 1.f / l1r;
    const int row0 = q0 + wr + g;
    const size_t base0 = (size_t)(b * N + row0) * C + hoff + 2 * tig;
    const size_t base1 = (size_t)(b * N + row0 + 8) * C + hoff + 2 * tig;
    float ss0 = 0.f, ss1 = 0.f;
    #pragma unroll
    for (int nt = 0; nt < 8; nt++) {
        float a0 = o[nt][0] * inv0, a1 = o[nt][1] * inv0;
        float b0 = o[nt][2] * inv1, b1 = o[nt][3] * inv1;
        ss0 += a0 * a0 + a1 * a1;
        ss1 += b0 * b0 + b1 * b1;
        uint32_t h0, l0, h1, l1;
        split_pack(a0, a1, h0, l0);
        split_pack(b0, b1, h1, l1);
        *(uint32_t*)(aoh + base0 + nt * 8) = h0;
        *(uint32_t*)(aol + base0 + nt * 8) = l0;
        *(uint32_t*)(aoh + base1 + nt * 8) = h1;
        *(uint32_t*)(aol + base1 + nt * 8) = l1;
    }
    ss0 += __shfl_xor_sync(0xffffffffu, ss0, 1);
    ss0 += __shfl_xor_sync(0xffffffffu, ss0, 2);
    ss1 += __shfl_xor_sync(0xffffffffu, ss1, 1);
    ss1 += __shfl_xor_sync(0xffffffffu, ss1, 2);
    if (tig == 0) {
        aopart[(size_t)h * M + b * N + row0]     = ss0;
        aopart[(size_t)h * M + b * N + row0 + 8] = ss1;
    }
}

// ---------------------------------------------------------------------------

extern "C" void kernel_launch(void* const* d_in, const int* in_sizes, int n_in,
                              void* d_out, int out_size) {
    (void)in_sizes; (void)n_in; (void)out_size;
    const float* x    = (const float*)d_in[0];
    const float* Wqkv = (const float*)d_in[1];
    const float* Wprj = (const float*)d_in[2];
    float* out = (float*)d_out;

    __nv_bfloat16 *pxh, *pxl, *pWqh, *pWql, *pWph, *pWpl, *paoh, *paol;
    __nv_bfloat16 *pq, *pk, *pv;
    float *pxn2, *papart;
    cudaGetSymbolAddress((void**)&pxh,  g_xh);
    cudaGetSymbolAddress((void**)&pxl,  g_xl);
    cudaGetSymbolAddress((void**)&pWqh, g_Wqh);
    cudaGetSymbolAddress((void**)&pWql, g_Wql);
    cudaGetSymbolAddress((void**)&pWph, g_Wph);
    cudaGetSymbolAddress((void**)&pWpl, g_Wpl);
    cudaGetSymbolAddress((void**)&paoh, g_aoh);
    cudaGetSymbolAddress((void**)&paol, g_aol);
    cudaGetSymbolAddress((void**)&pq,   g_q);
    cudaGetSymbolAddress((void**)&pk,   g_k);
    cudaGetSymbolAddress((void**)&pv,   g_v);
    cudaGetSymbolAddress((void**)&pxn2, g_xnorm2);
    cudaGetSymbolAddress((void**)&papart, g_aopart);

    cudaFuncSetAttribute(tc_gemm_kernel<0>,
                         cudaFuncAttributeMaxDynamicSharedMemorySize, GEMM_SMEM);
    cudaFuncSetAttribute(tc_gemm_kernel<1>,
                         cudaFuncAttributeMaxDynamicSharedMemorySize, GEMM_SMEM);
    cudaFuncSetAttribute(attn_mma_kernel,
                         cudaFuncAttributeMaxDynamicSharedMemorySize, ATTN_SMEM);

    // 1. prep
    prep_w_kernel<<<QKV_W, 128>>>(Wqkv, pWqh, pWql, 3 * C);
    prep_w_kernel<<<PRJ_W, 128>>>(Wprj, pWph, pWpl, C);
    prep_act_kernel<<<M, 128>>>(x, pxh, pxl, pxn2);

    // 2. bcos QKV projection -> plain bf16 head-major q/k/v (q pre-scaled)
    tc_gemm_kernel<1><<<dim3(QKV_W / BN, M / BM), 256, GEMM_SMEM>>>(
        pxh, pxl, pWqh, pWql, pxn2, nullptr, 0, pq, pk, pv);

    // 3. flash attention (plain bf16) -> bf16 split ao + per-head partials
    attn_mma_kernel<<<dim3(N / 128, B * H), 256, ATTN_SMEM>>>(
        pq, pk, pv, paoh, paol, papart);

    // 4. bcos output projection -> d_out (norms summed from partials)
    tc_gemm_kernel<0><<<dim3(PRJ_W / BN, M / BM), 256, GEMM_SMEM>>>(
        paoh, paol, pWph, pWpl, papart, out, PRJ_O,
        nullptr, nullptr, nullptr);
}